// round 8
// baseline (speedup 1.0000x reference)
#include <cuda_runtime.h>
#include <cuda_bf16.h>
#include <cstdint>

// TELIF: temporal-encoded LIF neuron scan — single fused kernel.
//   tx : [T, B, N] float32   (T=512, B=64, N=1024)
//   TE : [N, T]    float32
//   out: [T, B, N] float32 spikes
//
// Per (b, n), sequential in t:
//   th = th + v*TE[n,t] - (th - THRESHOLD)*BETA
//   v  = v*DECAY*(1 - y) + x
//   y  = (v > th) ? 1 : 0
//
// TE is staged gmem->smem with cp.async (no register footprint), in
// 32-timestep x 128-neuron tiles, double buffered, one barrier per tile.
// tx/ty are the dominant streams and stay on the register pipeline.

#define T_STEPS 512
#define B_DIM   64
#define N_DIM   1024
#define BN      (B_DIM * N_DIM)      // 65536
#define U       4                    // timesteps per chunk
#define NCHUNK  (T_STEPS / U)        // 128
#define TS_TILE 32                   // timesteps per TE smem tile
#define NTILES  (T_STEPS / TS_TILE)  // 16
#define BLK     128                  // threads (= neurons n per block)
#define ROWPAD  36                   // floats per smem row: 144B, 16B-aligned

#define REST      0.0f
#define DECAY     0.2f
#define THRESHOLD 0.3f
#define BETA      0.02f

// ---- cp.async helpers -----------------------------------------------------
__device__ __forceinline__ void cp_async16(uint32_t dst, const void* src) {
    asm volatile("cp.async.ca.shared.global [%0], [%1], 16;"
                 :: "r"(dst), "l"(src));
}
__device__ __forceinline__ void cp_async_commit() {
    asm volatile("cp.async.commit_group;" ::: "memory");
}
__device__ __forceinline__ void cp_async_wait0() {
    asm volatile("cp.async.wait_group 0;" ::: "memory");
}

// ---- TE tile (tile index k) -> smem buffer bb via cp.async ----------------
// Tile = 128 rows (n) x 32 floats (t) = 16KB = 1024 x 16B ops, 8 per thread.
// Row r of the tile is TE[n0 + r, k*32 .. k*32+31] (contiguous, 16B-aligned).
#define CPASYNC_TE(k, bb)                                                     \
    {                                                                         \
        const float* tep = TE + (size_t)n0 * T_STEPS + (k) * TS_TILE;         \
        _Pragma("unroll")                                                     \
        for (int j = 0; j < 8; j++) {                                         \
            const int idx = j * BLK + (int)threadIdx.x;                       \
            const int row = idx >> 3, c4 = idx & 7;                           \
            cp_async16(smem_base + (uint32_t)(((bb) * BLK + row) * ROWPAD     \
                                              + c4 * 4) * 4u,                 \
                       tep + (size_t)row * T_STEPS + c4 * 4);                 \
        }                                                                     \
        cp_async_commit();                                                    \
    }

// ---- tx chunk prefetch (streaming) ----------------------------------------
#define TXLOAD(xq, c)                                                         \
    {                                                                         \
        _Pragma("unroll")                                                     \
        for (int u = 0; u < U; u++)                                           \
            xq[u] = __ldcs(&tx[((size_t)(c) * U + u) * BN + g]);              \
    }

// ---- one timestep (arithmetic form identical to the rel_err==0.0 version) -
#define ONE_STEP(x, te, c, u)                                                 \
    {                                                                         \
        th = th + v * (te) - (th - THRESHOLD) * BETA;                         \
        v  = v * DECAY * (1.0f - y) + (x);                                    \
        y  = (v > th) ? 1.0f : 0.0f;                                          \
        __stcs(&ty[((size_t)(c) * U + (u)) * BN + g], y);                     \
    }

// ---- one chunk: TE row slice as one LDS.128 (conflict-free) ---------------
#define COMPUTE_CHUNK(xq, bb, iloc, c)                                        \
    {                                                                         \
        const float4 t4 = *reinterpret_cast<const float4*>(                   \
            &te_s[((bb) * BLK + (int)threadIdx.x) * ROWPAD + (iloc) * U]);    \
        ONE_STEP(xq[0], t4.x, c, 0)                                           \
        ONE_STEP(xq[1], t4.y, c, 1)                                           \
        ONE_STEP(xq[2], t4.z, c, 2)                                           \
        ONE_STEP(xq[3], t4.w, c, 3)                                           \
    }

__global__ void __launch_bounds__(BLK) telif_kernel(
    const float* __restrict__ tx,
    const float* __restrict__ TE,
    float* __restrict__ ty)
{
    __shared__ float te_s[2 * BLK * ROWPAD];   // 36 KB, double buffered

    const int g  = blockIdx.x * BLK + threadIdx.x;          // g = b*N + n
    const int n0 = (blockIdx.x & (N_DIM / BLK - 1)) * BLK;  // block n origin
    const uint32_t smem_base = (uint32_t)__cvta_generic_to_shared(te_s);

    float v  = REST;
    float y  = 0.0f;
    float th = THRESHOLD;

    float x0[U], x1[U], x2[U], x3[U];   // tx pipeline, distance 4 chunks

    // prologue
    CPASYNC_TE(0, 0)
    TXLOAD(x0, 0) TXLOAD(x1, 1) TXLOAD(x2, 2) TXLOAD(x3, 3)
    cp_async_wait0();
    __syncthreads();
    CPASYNC_TE(1, 1)

    #pragma unroll 1
    for (int tile = 0; tile < NTILES; tile++) {
        const int b  = tile & 1;
        const int c0 = tile * 8;

        COMPUTE_CHUNK(x0, b, 0, c0 + 0) if (c0 + 4  < NCHUNK) TXLOAD(x0, c0 + 4)
        COMPUTE_CHUNK(x1, b, 1, c0 + 1) if (c0 + 5  < NCHUNK) TXLOAD(x1, c0 + 5)
        COMPUTE_CHUNK(x2, b, 2, c0 + 2) if (c0 + 6  < NCHUNK) TXLOAD(x2, c0 + 6)
        COMPUTE_CHUNK(x3, b, 3, c0 + 3) if (c0 + 7  < NCHUNK) TXLOAD(x3, c0 + 7)
        COMPUTE_CHUNK(x0, b, 4, c0 + 4) if (c0 + 8  < NCHUNK) TXLOAD(x0, c0 + 8)
        COMPUTE_CHUNK(x1, b, 5, c0 + 5) if (c0 + 9  < NCHUNK) TXLOAD(x1, c0 + 9)
        COMPUTE_CHUNK(x2, b, 6, c0 + 6) if (c0 + 10 < NCHUNK) TXLOAD(x2, c0 + 10)
        COMPUTE_CHUNK(x3, b, 7, c0 + 7) if (c0 + 11 < NCHUNK) TXLOAD(x3, c0 + 11)

        if (tile + 1 < NTILES) {
            cp_async_wait0();            // tile+1's TE has landed
            __syncthreads();             // everyone done with buffer b
            if (tile + 2 < NTILES) CPASYNC_TE(tile + 2, b)  // refill b
        }
    }
}

// ---------------------------------------------------------------------------
extern "C" void kernel_launch(void* const* d_in, const int* in_sizes, int n_in,
                              void* d_out, int out_size) {
    const float* tx = (const float*)d_in[0];   // [T, B, N]
    const float* TE = (const float*)d_in[1];   // [N, T]
    float* ty = (float*)d_out;                 // [T, B, N]
    (void)in_sizes; (void)n_in; (void)out_size;

    telif_kernel<<<BN / BLK, BLK>>>(tx, TE, ty);
}

// round 10
// speedup vs baseline: 1.2238x; 1.2238x over previous
#include <cuda_runtime.h>
#include <cuda_bf16.h>

// TELIF: temporal-encoded LIF neuron scan.
//   tx : [T, B, N] float32   (T=512, B=64, N=1024)
//   TE : [N, T]    float32
//   out: [T, B, N] float32 spikes
//
// Per (b, n), sequential in t:
//   th = th + v*TE[n,t] - (th - THRESHOLD)*BETA
//   v  = v*DECAY*(1 - y) + x
//   y  = (v > th) ? 1 : 0
//
// Two kernels: (1) transpose TE -> g_TEt so the hot loop's TE loads are
// warp-coalesced and L2-resident; (2) scan with one thread per (b,n) chain
// and a depth-8 register pipeline (all buffer indices compile-time).

#define T_STEPS 512
#define B_DIM   64
#define N_DIM   1024
#define BN      (B_DIM * N_DIM)      // 65536
#define U       4                    // timesteps per chunk
#define NCHUNK  (T_STEPS / U)        // 128

#define REST      0.0f
#define DECAY     0.2f
#define THRESHOLD 0.3f
#define BETA      0.02f

// Transposed temporal encoding: TEt[t][n]  (2 MB static device scratch)
__device__ float g_TEt[T_STEPS * N_DIM];

// ---------------------------------------------------------------------------
// Pre-pass: transpose TE [N, T] -> g_TEt [T, N].
// ---------------------------------------------------------------------------
__global__ void transpose_te_kernel(const float* __restrict__ TE) {
    __shared__ float tile[32][33];
    const int tbase = blockIdx.x * 32;
    const int nbase = blockIdx.y * 32;

    #pragma unroll
    for (int r = threadIdx.y; r < 32; r += 8)
        tile[r][threadIdx.x] = TE[(nbase + r) * T_STEPS + tbase + threadIdx.x];
    __syncthreads();
    #pragma unroll
    for (int r = threadIdx.y; r < 32; r += 8)
        __stcs(&g_TEt[(tbase + r) * N_DIM + nbase + threadIdx.x],
               tile[threadIdx.x][r]);
}

// ---------------------------------------------------------------------------
// Main scan. One thread per (b,n). 8 register buffers of U=4 timesteps,
// prefetch distance 7 chunks (~28 tx + 28 TE loads in flight per thread),
// every buffer index a compile-time constant (no local-memory spill).
// tx streamed (__ldcs, read-once), ty streamed out (__stcs), TE L2-cached.
// ---------------------------------------------------------------------------

#define LOAD_CHUNK(xq, tq, c)                                         \
    {                                                                 \
        _Pragma("unroll")                                             \
        for (int u = 0; u < U; u++) {                                 \
            xq[u] = __ldcs(&tx[((c) * U + u) * BN + g]);              \
            tq[u] = g_TEt[((c) * U + u) * N_DIM + n];                 \
        }                                                             \
    }

// arithmetic form identical to the rel_err==0.0 version
#define COMPUTE_CHUNK(xq, tq, c)                                      \
    {                                                                 \
        _Pragma("unroll")                                             \
        for (int u = 0; u < U; u++) {                                 \
            const float x  = xq[u];                                   \
            const float te = tq[u];                                   \
            th = th + v * te - (th - THRESHOLD) * BETA;               \
            v  = v * DECAY * (1.0f - y) + x;                          \
            y  = (v > th) ? 1.0f : 0.0f;                              \
            __stcs(&ty[((c) * U + u) * BN + g], y);                   \
        }                                                             \
    }

__global__ void __launch_bounds__(64) telif_kernel(
    const float* __restrict__ tx,
    float* __restrict__ ty)
{
    const int g = blockIdx.x * blockDim.x + threadIdx.x;  // g = b*N + n
    const int n = g & (N_DIM - 1);

    float v  = REST;
    float y  = 0.0f;
    float th = THRESHOLD;

    float xA[U], tA[U], xB[U], tB[U], xC[U], tC[U], xD[U], tD[U];
    float xE[U], tE[U], xF[U], tF[U], xG[U], tG[U], xH[U], tH[U];

    // prologue: chunks 0..6 into A..G
    LOAD_CHUNK(xA, tA, 0)
    LOAD_CHUNK(xB, tB, 1)
    LOAD_CHUNK(xC, tC, 2)
    LOAD_CHUNK(xD, tD, 3)
    LOAD_CHUNK(xE, tE, 4)
    LOAD_CHUNK(xF, tF, 5)
    LOAD_CHUNK(xG, tG, 6)

    #pragma unroll 1
    for (int c = 0; c < NCHUNK; c += 8) {
        LOAD_CHUNK(xH, tH, c + 7)
        COMPUTE_CHUNK(xA, tA, c)
        if (c +  8 < NCHUNK) LOAD_CHUNK(xA, tA, c + 8)
        COMPUTE_CHUNK(xB, tB, c + 1)
        if (c +  9 < NCHUNK) LOAD_CHUNK(xB, tB, c + 9)
        COMPUTE_CHUNK(xC, tC, c + 2)
        if (c + 10 < NCHUNK) LOAD_CHUNK(xC, tC, c + 10)
        COMPUTE_CHUNK(xD, tD, c + 3)
        if (c + 11 < NCHUNK) LOAD_CHUNK(xD, tD, c + 11)
        COMPUTE_CHUNK(xE, tE, c + 4)
        if (c + 12 < NCHUNK) LOAD_CHUNK(xE, tE, c + 12)
        COMPUTE_CHUNK(xF, tF, c + 5)
        if (c + 13 < NCHUNK) LOAD_CHUNK(xF, tF, c + 13)
        COMPUTE_CHUNK(xG, tG, c + 6)
        if (c + 14 < NCHUNK) LOAD_CHUNK(xG, tG, c + 14)
        COMPUTE_CHUNK(xH, tH, c + 7)
    }
}

// ---------------------------------------------------------------------------
extern "C" void kernel_launch(void* const* d_in, const int* in_sizes, int n_in,
                              void* d_out, int out_size) {
    const float* tx = (const float*)d_in[0];   // [T, B, N]
    const float* TE = (const float*)d_in[1];   // [N, T]
    float* ty = (float*)d_out;                 // [T, B, N]
    (void)in_sizes; (void)n_in; (void)out_size;

    dim3 tgrid(T_STEPS / 32, N_DIM / 32);
    dim3 tblock(32, 8);
    transpose_te_kernel<<<tgrid, tblock>>>(TE);

    telif_kernel<<<BN / 64, 64>>>(tx, ty);
}

// round 11
// speedup vs baseline: 1.2467x; 1.0187x over previous
#include <cuda_runtime.h>
#include <cuda_bf16.h>

// TELIF: temporal-encoded LIF neuron scan.
//   tx : [T, B, N] float32   (T=512, B=64, N=1024)
//   TE : [N, T]    float32
//   out: [T, B, N] float32 spikes
//
// Per (b, n), sequential in t:
//   th = th + v*TE[n,t] - (th - THRESHOLD)*BETA
//   v  = v*DECAY*(1 - y) + x
//   y  = (v > th) ? 1 : 0
//
// Two kernels: (1) transpose TE -> g_TEt so the hot loop's TE loads are
// warp-coalesced and L2-resident; (2) scan, one thread per (b,n) chain,
// depth-4 register pipeline with a guard-free steady state + drain.

#define T_STEPS 512
#define B_DIM   64
#define N_DIM   1024
#define BN      (B_DIM * N_DIM)      // 65536
#define U       4                    // timesteps per chunk
#define NCHUNK  (T_STEPS / U)        // 128

#define REST      0.0f
#define DECAY     0.2f
#define THRESHOLD 0.3f
#define BETA      0.02f

// Transposed temporal encoding: TEt[t][n]  (2 MB static device scratch)
__device__ float g_TEt[T_STEPS * N_DIM];

// ---------------------------------------------------------------------------
// Pre-pass: transpose TE [N, T] -> g_TEt [T, N].
// ---------------------------------------------------------------------------
__global__ void transpose_te_kernel(const float* __restrict__ TE) {
    __shared__ float tile[32][33];
    const int tbase = blockIdx.x * 32;
    const int nbase = blockIdx.y * 32;

    #pragma unroll
    for (int r = threadIdx.y; r < 32; r += 8)
        tile[r][threadIdx.x] = TE[(nbase + r) * T_STEPS + tbase + threadIdx.x];
    __syncthreads();
    #pragma unroll
    for (int r = threadIdx.y; r < 32; r += 8)
        __stcs(&g_TEt[(tbase + r) * N_DIM + nbase + threadIdx.x],
               tile[threadIdx.x][r]);
}

// ---------------------------------------------------------------------------
// Main scan.
// ---------------------------------------------------------------------------

#define LOAD_CHUNK(xq, tq, c)                                         \
    {                                                                 \
        _Pragma("unroll")                                             \
        for (int u = 0; u < U; u++) {                                 \
            xq[u] = __ldcs(&tx[((c) * U + u) * BN + g]);              \
            tq[u] = g_TEt[((c) * U + u) * N_DIM + n];                 \
        }                                                             \
    }

// th-update kept in the measured rel_err==0.0 form.
// v-update: y is exactly 0.0 or 1.0, so  v*DECAY*(1-y)+x  ==  y?x:(v*DECAY+x)
// bitwise (multiply by exact 1/0 commutes with rounding in either the
// FMUL+FADD or FFMA compilation). Saves one FADD and one FMUL per step.
#define COMPUTE_CHUNK(xq, tq, c)                                      \
    {                                                                 \
        _Pragma("unroll")                                             \
        for (int u = 0; u < U; u++) {                                 \
            const float x  = xq[u];                                   \
            const float te = tq[u];                                   \
            th = th + v * te - (th - THRESHOLD) * BETA;               \
            const float vd = v * DECAY + x;                           \
            v  = (y != 0.0f) ? x : vd;                                \
            y  = (v > th) ? 1.0f : 0.0f;                              \
            __stcs(&ty[((c) * U + u) * BN + g], y);                   \
        }                                                             \
    }

__global__ void __launch_bounds__(128) telif_kernel(
    const float* __restrict__ tx,
    float* __restrict__ ty)
{
    const int g = blockIdx.x * blockDim.x + threadIdx.x;  // g = b*N + n
    const int n = g & (N_DIM - 1);

    float v  = REST;
    float y  = 0.0f;
    float th = THRESHOLD;

    float xA[U], tA[U], xB[U], tB[U], xC[U], tC[U], xD[U], tD[U];

    // prologue: chunks 0..3 into A..D
    LOAD_CHUNK(xA, tA, 0)
    LOAD_CHUNK(xB, tB, 1)
    LOAD_CHUNK(xC, tC, 2)
    LOAD_CHUNK(xD, tD, 3)

    // steady state: completely guard-free (loads c+4..c+7 always in range)
    #pragma unroll 1
    for (int c = 0; c < NCHUNK - 4; c += 4) {
        COMPUTE_CHUNK(xA, tA, c)
        LOAD_CHUNK(xA, tA, c + 4)
        COMPUTE_CHUNK(xB, tB, c + 1)
        LOAD_CHUNK(xB, tB, c + 5)
        COMPUTE_CHUNK(xC, tC, c + 2)
        LOAD_CHUNK(xC, tC, c + 6)
        COMPUTE_CHUNK(xD, tD, c + 3)
        LOAD_CHUNK(xD, tD, c + 7)
    }

    // drain: last 4 chunks, no loads
    COMPUTE_CHUNK(xA, tA, NCHUNK - 4)
    COMPUTE_CHUNK(xB, tB, NCHUNK - 3)
    COMPUTE_CHUNK(xC, tC, NCHUNK - 2)
    COMPUTE_CHUNK(xD, tD, NCHUNK - 1)
}

// ---------------------------------------------------------------------------
extern "C" void kernel_launch(void* const* d_in, const int* in_sizes, int n_in,
                              void* d_out, int out_size) {
    const float* tx = (const float*)d_in[0];   // [T, B, N]
    const float* TE = (const float*)d_in[1];   // [N, T]
    float* ty = (float*)d_out;                 // [T, B, N]
    (void)in_sizes; (void)n_in; (void)out_size;

    dim3 tgrid(T_STEPS / 32, N_DIM / 32);
    dim3 tblock(32, 8);
    transpose_te_kernel<<<tgrid, tblock>>>(TE);

    telif_kernel<<<BN / 128, 128>>>(tx, ty);
}